// round 1
// baseline (speedup 1.0000x reference)
#include <cuda_runtime.h>
#include <cuda_bf16.h>
#include <math.h>

#define B_    4
#define N_    4096
#define DIN_  512
#define DOUT_ 128
#define MAXDEG 256
#define NEG_BIG -1e30f

// ---------------- scratch (static device memory; no allocs) ----------------
__device__ float g_wh[B_ * N_ * DOUT_];     // x @ W            (8 MB)
__device__ float g_out[B_ * N_ * DOUT_];    // att @ wh         (8 MB)
__device__ float g_s[B_ * N_];              // wh @ a_src
__device__ float g_d[B_ * N_];              // wh @ a_dst
__device__ float g_sumwh[B_ * DOUT_];       // column sums of wh per graph (deg==0 fallback)
__device__ int   g_cols[N_ * MAXDEG];       // CSR cols (fixed capacity)
__device__ int   g_deg[N_];

// ---------------- zero accumulator ----------------
__global__ void zero_kernel() {
    int t = threadIdx.x;
    if (t < B_ * DOUT_) g_sumwh[t] = 0.0f;
}

// ---------------- CSR build: warp per row, ballot compaction (ordered) -----
__global__ void csr_build_kernel(const float* __restrict__ adj) {
    int warp = (blockIdx.x * blockDim.x + threadIdx.x) >> 5;
    int lane = threadIdx.x & 31;
    if (warp >= N_) return;
    const float* row = adj + (size_t)warp * N_;
    int cnt = 0;
    for (int base = 0; base < N_; base += 32) {
        float v = row[base + lane];
        unsigned m = __ballot_sync(0xffffffffu, v > 0.0f);
        if (v > 0.0f) {
            int pos = cnt + __popc(m & ((1u << lane) - 1u));
            if (pos < MAXDEG) g_cols[warp * MAXDEG + pos] = base + lane;
        }
        cnt += __popc(m);
    }
    if (lane == 0) g_deg[warp] = cnt < MAXDEG ? cnt : MAXDEG;
}

// ---------------- SGEMM: wh = x @ W   (M=16384, K=512, N=128) --------------
// 128x128 block tile, BK=8, 256 threads, 8x8 per-thread microtile.
__global__ __launch_bounds__(256) void gemm_wh_kernel(
    const float* __restrict__ A, const float* __restrict__ W) {
    __shared__ float As[8][128];
    __shared__ float Bs[8][128];

    int tid = threadIdx.x;
    int blockRow = blockIdx.x * 128;
    int arow = tid >> 1, acol = (tid & 1) * 4;   // A tile load: 128 rows x 8 k
    int brow = tid >> 5, bcol = (tid & 31) * 4;  // B tile load: 8 k x 128 n
    int ty = tid >> 4, tx = tid & 15;

    float acc[8][8];
#pragma unroll
    for (int i = 0; i < 8; i++)
#pragma unroll
        for (int j = 0; j < 8; j++) acc[i][j] = 0.0f;

    const float* Ablk = A + (size_t)blockRow * DIN_;

    for (int k0 = 0; k0 < DIN_; k0 += 8) {
        float4 av = *(const float4*)(Ablk + (size_t)arow * DIN_ + k0 + acol);
        As[acol + 0][arow] = av.x;
        As[acol + 1][arow] = av.y;
        As[acol + 2][arow] = av.z;
        As[acol + 3][arow] = av.w;
        float4 bv = *(const float4*)(W + (size_t)(k0 + brow) * DOUT_ + bcol);
        *(float4*)&Bs[brow][bcol] = bv;
        __syncthreads();
#pragma unroll
        for (int kk = 0; kk < 8; kk++) {
            float rm[8], rn[8];
#pragma unroll
            for (int i = 0; i < 8; i++) rm[i] = As[kk][ty * 8 + i];
#pragma unroll
            for (int j = 0; j < 8; j++) rn[j] = Bs[kk][tx * 8 + j];
#pragma unroll
            for (int i = 0; i < 8; i++)
#pragma unroll
                for (int j = 0; j < 8; j++) acc[i][j] += rm[i] * rn[j];
        }
        __syncthreads();
    }

#pragma unroll
    for (int i = 0; i < 8; i++) {
        int row = blockRow + ty * 8 + i;
        float4 v0 = make_float4(acc[i][0], acc[i][1], acc[i][2], acc[i][3]);
        float4 v1 = make_float4(acc[i][4], acc[i][5], acc[i][6], acc[i][7]);
        *(float4*)&g_wh[(size_t)row * DOUT_ + tx * 8 + 0] = v0;
        *(float4*)&g_wh[(size_t)row * DOUT_ + tx * 8 + 4] = v1;
    }
}

// ---------------- s, d and per-graph column sums ----------------
// warp per row; 8 rows per block (block never crosses a graph boundary).
__global__ __launch_bounds__(256) void sd_kernel(const float* __restrict__ a) {
    __shared__ float ssum[DOUT_];
    int tid = threadIdx.x, lane = tid & 31, w = tid >> 5;
    if (tid < DOUT_) ssum[tid] = 0.0f;
    __syncthreads();

    int r = blockIdx.x * 8 + w;  // row in [0, B*N)
    const float4* whr = (const float4*)&g_wh[(size_t)r * DOUT_];
    const float4* as4 = (const float4*)a;            // a_src
    const float4* ad4 = (const float4*)(a + DOUT_);  // a_dst

    float4 v = whr[lane];
    float4 sa = as4[lane];
    float4 da = ad4[lane];
    float sv = v.x * sa.x + v.y * sa.y + v.z * sa.z + v.w * sa.w;
    float dv = v.x * da.x + v.y * da.y + v.z * da.z + v.w * da.w;
#pragma unroll
    for (int off = 16; off > 0; off >>= 1) {
        sv += __shfl_xor_sync(0xffffffffu, sv, off);
        dv += __shfl_xor_sync(0xffffffffu, dv, off);
    }
    if (lane == 0) { g_s[r] = sv; g_d[r] = dv; }

    atomicAdd(&ssum[lane * 4 + 0], v.x);
    atomicAdd(&ssum[lane * 4 + 1], v.y);
    atomicAdd(&ssum[lane * 4 + 2], v.z);
    atomicAdd(&ssum[lane * 4 + 3], v.w);
    __syncthreads();
    if (tid < DOUT_) {
        int b = (blockIdx.x * 8) / N_;
        atomicAdd(&g_sumwh[b * DOUT_ + tid], ssum[tid]);
    }
}

// ---------------- attention SpMM: out = softmax(mask(leaky(e))) @ wh -------
// warp per (graph,row). e/p staged in shared memory per warp.
__global__ __launch_bounds__(256) void attn_kernel() {
    __shared__ float sh_p[8][MAXDEG];
    __shared__ int   sh_j[8][MAXDEG];
    int gw = (blockIdx.x * blockDim.x + threadIdx.x) >> 5;
    int lane = threadIdx.x & 31;
    int w = (threadIdx.x >> 5);
    if (gw >= B_ * N_) return;
    int b = gw / N_, i = gw % N_;
    int deg = g_deg[i];

    float4* outr = (float4*)&g_out[(size_t)gw * DOUT_];

    if (deg == 0) {
        // uniform softmax over all N columns -> mean of wh
        const float4* sw = (const float4*)&g_sumwh[b * DOUT_];
        float4 m = sw[lane];
        float inv = 1.0f / (float)N_;
        outr[lane] = make_float4(m.x * inv, m.y * inv, m.z * inv, m.w * inv);
        return;
    }

    float si = g_s[gw];
    float mx = NEG_BIG;
    for (int t = lane; t < deg; t += 32) {
        int j = g_cols[i * MAXDEG + t];
        float e = si + g_d[(size_t)b * N_ + j];
        e = e > 0.0f ? e : 0.01f * e;  // leaky relu
        sh_j[w][t] = j;
        sh_p[w][t] = e;
        mx = fmaxf(mx, e);
    }
#pragma unroll
    for (int off = 16; off > 0; off >>= 1)
        mx = fmaxf(mx, __shfl_xor_sync(0xffffffffu, mx, off));
    __syncwarp();

    float se = 0.0f;
    for (int t = lane; t < deg; t += 32) {
        float p = expf(sh_p[w][t] - mx);
        sh_p[w][t] = p;
        se += p;
    }
#pragma unroll
    for (int off = 16; off > 0; off >>= 1)
        se += __shfl_xor_sync(0xffffffffu, se, off);
    float inv = 1.0f / se;
    __syncwarp();

    float4 acc = make_float4(0.f, 0.f, 0.f, 0.f);
    for (int k = 0; k < deg; k++) {
        float p = sh_p[w][k] * inv;
        int j = sh_j[w][k];
        float4 v = ((const float4*)&g_wh[((size_t)b * N_ + j) * DOUT_])[lane];
        acc.x += p * v.x; acc.y += p * v.y; acc.z += p * v.z; acc.w += p * v.w;
    }
    outr[lane] = acc;
}

// ---------------- final: y = relu(adj @ out) ----------------
__global__ __launch_bounds__(256) void final_kernel(float* __restrict__ y) {
    int gw = (blockIdx.x * blockDim.x + threadIdx.x) >> 5;
    int lane = threadIdx.x & 31;
    if (gw >= B_ * N_) return;
    int b = gw / N_, i = gw % N_;
    int deg = g_deg[i];

    float4 acc = make_float4(0.f, 0.f, 0.f, 0.f);
    for (int k = 0; k < deg; k++) {
        int j = g_cols[i * MAXDEG + k];  // uniform across warp -> broadcast
        float4 v = ((const float4*)&g_out[((size_t)b * N_ + j) * DOUT_])[lane];
        acc.x += v.x; acc.y += v.y; acc.z += v.z; acc.w += v.w;
    }
    float4 r = make_float4(fmaxf(acc.x, 0.f), fmaxf(acc.y, 0.f),
                           fmaxf(acc.z, 0.f), fmaxf(acc.w, 0.f));
    ((float4*)&y[(size_t)gw * DOUT_])[lane] = r;
}

// ---------------- launch ----------------
extern "C" void kernel_launch(void* const* d_in, const int* in_sizes, int n_in,
                              void* d_out, int out_size) {
    const float* x   = (const float*)d_in[0];  // (B, N, DIN)
    const float* adj = (const float*)d_in[1];  // (N, N)
    const float* wts = (const float*)d_in[2];  // (DIN, DOUT)
    const float* a   = (const float*)d_in[3];  // (2*DOUT, 1)
    float* y = (float*)d_out;

    zero_kernel<<<1, 512>>>();
    csr_build_kernel<<<N_ / 8, 256>>>(adj);
    gemm_wh_kernel<<<(B_ * N_) / 128, 256>>>(x, wts);
    sd_kernel<<<(B_ * N_) / 8, 256>>>(a);
    attn_kernel<<<(B_ * N_) / 8, 256>>>();
    final_kernel<<<(B_ * N_) / 8, 256>>>(y);
}

// round 3
// speedup vs baseline: 1.7438x; 1.7438x over previous
#include <cuda_runtime.h>
#include <cuda_bf16.h>
#include <math.h>
#include <stdint.h>

#define B_    4
#define N_    4096
#define DIN_  512
#define DOUT_ 128
#define MAXDEG 256
#define NEG_BIG -1e30f

// ---------------- scratch (static device memory; no allocs) ----------------
__device__ float g_wh[B_ * N_ * DOUT_];     // x @ W            (8 MB)
__device__ float g_out[B_ * N_ * DOUT_];    // att @ wh         (8 MB)
__device__ float g_s[B_ * N_];              // wh @ a_src
__device__ float g_d[B_ * N_];              // wh @ a_dst
__device__ float g_sumwh[B_ * DOUT_];       // per-graph colsum (deg==0 fallback)
__device__ int   g_cols[N_ * MAXDEG];
__device__ int   g_deg[N_];

// ============================ helpers =======================================
__device__ __forceinline__ uint32_t smem_u32(const void* p) {
    uint32_t a;
    asm("{ .reg .u64 t; cvta.to.shared.u64 t, %1; cvt.u32.u64 %0, t; }" : "=r"(a) : "l"(p));
    return a;
}
__device__ __forceinline__ void ldm_x4(uint32_t* f, uint32_t addr) {
    asm volatile("ldmatrix.sync.aligned.m8n8.x4.shared.b16 {%0,%1,%2,%3}, [%4];"
                 : "=r"(f[0]), "=r"(f[1]), "=r"(f[2]), "=r"(f[3]) : "r"(addr));
}
__device__ __forceinline__ void ldm_x4t(uint32_t* f, uint32_t addr) {
    asm volatile("ldmatrix.sync.aligned.m8n8.x4.trans.shared.b16 {%0,%1,%2,%3}, [%4];"
                 : "=r"(f[0]), "=r"(f[1]), "=r"(f[2]), "=r"(f[3]) : "r"(addr));
}
__device__ __forceinline__ void mma_bf16(float* c, const uint32_t* a, const uint32_t* b) {
    asm volatile(
        "mma.sync.aligned.m16n8k16.row.col.f32.bf16.bf16.f32 "
        "{%0,%1,%2,%3}, {%4,%5,%6,%7}, {%8,%9}, {%0,%1,%2,%3};"
        : "+f"(c[0]), "+f"(c[1]), "+f"(c[2]), "+f"(c[3])
        : "r"(a[0]), "r"(a[1]), "r"(a[2]), "r"(a[3]), "r"(b[0]), "r"(b[1]));
}
__device__ __forceinline__ uint32_t pack_bf16(float x, float y) {
    __nv_bfloat16 hx = __float2bfloat16_rn(x);
    __nv_bfloat16 hy = __float2bfloat16_rn(y);
    return ((uint32_t)__bfloat16_as_ushort(hy) << 16) | __bfloat16_as_ushort(hx);
}

// ============================ small kernels =================================
__global__ void zero_kernel() {
    int t = threadIdx.x;
    if (t < B_ * DOUT_) g_sumwh[t] = 0.0f;
}

__global__ void csr_build_kernel(const float* __restrict__ adj) {
    int warp = (blockIdx.x * blockDim.x + threadIdx.x) >> 5;
    int lane = threadIdx.x & 31;
    if (warp >= N_) return;
    const float4* row = (const float4*)(adj + (size_t)warp * N_);
    int cnt = 0;
    for (int base = 0; base < N_; base += 128) {
        float4 v = row[(base >> 2) + lane];
        float c4[4] = {v.x, v.y, v.z, v.w};
#pragma unroll
        for (int c = 0; c < 4; c++) {
            unsigned m = __ballot_sync(0xffffffffu, c4[c] > 0.0f);
            if (c4[c] > 0.0f) {
                int pos = cnt + __popc(m & ((1u << lane) - 1u));
                if (pos < MAXDEG) g_cols[warp * MAXDEG + pos] = base + lane * 4 + c;
            }
            cnt += __popc(m);
        }
    }
    if (lane == 0) g_deg[warp] = cnt < MAXDEG ? cnt : MAXDEG;
}

// ============ HMMA GEMM: wh = x @ W  (M=16384, N=128, K=512) ===============
// 128x128 CTA tile, 8 warps of 32x64. K chunks of 32, bf16 3-term split
// (hi*hi + hi*lo + lo*hi), double-buffered smem + register prefetch.
// smem A tile: per row 128B = [hi: 32 bf16 | lo: 32 bf16], granule-XOR swizzle.
// smem B tile: hi then lo, each 32 rows x 256B (128 bf16), granule-XOR swizzle.
#define KC 32
#define NCH (DIN_ / KC)          // 16 chunks
#define A_STG 16384              // 128 rows * 128B
#define B_STG 16384              // hi 8KB + lo 8KB
#define SM_A 0
#define SM_B (2 * A_STG)
#define SM_SD (SM_B + 2 * B_STG)          // s_sm[128], d_sm[128]
#define SM_AV (SM_SD + 1024)              // a_s[128], a_d[128]
#define SMEM_TOTAL (SM_AV + 1024)

__device__ __forceinline__ uint32_t a_off(int r, int gran) {
    return (uint32_t)(r * 128 + ((gran ^ (r & 7)) << 4));
}
__device__ __forceinline__ uint32_t b_off(int k, int gran) {
    return (uint32_t)(k * 256 + (((gran & 7) ^ (k & 7) ^ (gran & 8)) << 4) + ((gran & 8) << 4));
}
// simpler, correct: phys_gran = gran ^ (k&7) only flips low 3 bits
__device__ __forceinline__ uint32_t b_off2(int k, int gran) {
    return (uint32_t)(k * 256 + ((gran ^ (k & 7)) << 4));
}

__global__ __launch_bounds__(256, 1) void gemm_hmma_kernel(
    const float* __restrict__ x, const float* __restrict__ W,
    const float* __restrict__ a) {
    extern __shared__ char smem[];
    const uint32_t sb = smem_u32(smem);
    const int tid = threadIdx.x;
    const int wid = tid >> 5, lane = tid & 31;
    const int wm = wid >> 1, wn = wid & 1;   // warp tile: rows wm*32, cols wn*64
    const int tig = lane & 3, grp = lane >> 2;

    float* s_sm = (float*)(smem + SM_SD);
    float* d_sm = (float*)(smem + SM_SD + 512);
    float* a_s  = (float*)(smem + SM_AV);
    float* a_d  = (float*)(smem + SM_AV + 512);
    if (tid < 128) {
        s_sm[tid] = 0.0f; d_sm[tid] = 0.0f;
        a_s[tid] = a[tid]; a_d[tid] = a[DOUT_ + tid];
    }

    const int R0 = blockIdx.x * 128;
    // global load coords
    const int arow = tid >> 1, akoff = (tid & 1) * 16;
    const int bk = tid >> 3,  bn0 = (tid & 7) * 16;
    const float* pA = x + (size_t)(R0 + arow) * DIN_ + akoff;
    const float* pB = W + (size_t)bk * DOUT_ + bn0;

    float acc[2][8][4];
#pragma unroll
    for (int i = 0; i < 2; i++)
#pragma unroll
        for (int j = 0; j < 8; j++)
#pragma unroll
            for (int q = 0; q < 4; q++) acc[i][j][q] = 0.0f;

    float4 ra[4], rb[4];
    // prologue: chunk 0
#pragma unroll
    for (int i = 0; i < 4; i++) ra[i] = *(const float4*)(pA + i * 4);
#pragma unroll
    for (int i = 0; i < 4; i++) rb[i] = *(const float4*)(pB + i * 4);

    for (int c = 0; c < NCH; c++) {
        const int buf = c & 1;
        char* Abuf = smem + SM_A + buf * A_STG;
        char* Bhi  = smem + SM_B + buf * B_STG;
        char* Blo  = Bhi + 8192;

        // store prefetched chunk c into smem (converted)
        {
            const float* fa = (const float*)ra;
#pragma unroll
            for (int p = 0; p < 8; p++) {
                float f0 = fa[2 * p], f1 = fa[2 * p + 1];
                uint32_t hv = pack_bf16(f0, f1);
                float l0 = f0 - __bfloat162float(__float2bfloat16_rn(f0));
                float l1 = f1 - __bfloat162float(__float2bfloat16_rn(f1));
                uint32_t lv = pack_bf16(l0, l1);
                int kl = akoff + 2 * p;
                int gr = kl >> 3, wi = (kl & 7) * 2;
                *(uint32_t*)(Abuf + a_off(arow, gr) + wi)     = hv;
                *(uint32_t*)(Abuf + a_off(arow, gr + 4) + wi) = lv;
            }
            const float* fb = (const float*)rb;
#pragma unroll
            for (int p = 0; p < 8; p++) {
                float f0 = fb[2 * p], f1 = fb[2 * p + 1];
                uint32_t hv = pack_bf16(f0, f1);
                float l0 = f0 - __bfloat162float(__float2bfloat16_rn(f0));
                float l1 = f1 - __bfloat162float(__float2bfloat16_rn(f1));
                uint32_t lv = pack_bf16(l0, l1);
                int n = bn0 + 2 * p;
                int gr = n >> 3, wi = (n & 7) * 2;
                *(uint32_t*)(Bhi + b_off2(bk, gr) + wi) = hv;
                *(uint32_t*)(Blo + b_off2(bk, gr) + wi) = lv;
            }
        }
        __syncthreads();

        // prefetch chunk c+1 into regs
        if (c + 1 < NCH) {
            const float* qA = pA + (c + 1) * KC;
            const float* qB = pB + (size_t)(c + 1) * KC * DOUT_;
#pragma unroll
            for (int i = 0; i < 4; i++) ra[i] = *(const float4*)(qA + i * 4);
#pragma unroll
            for (int i = 0; i < 4; i++) rb[i] = *(const float4*)(qB + i * 4);
        }

        // ---- MMA on chunk c ----
        const uint32_t Abase = sb + SM_A + buf * A_STG;
        const uint32_t BhiB  = sb + SM_B + buf * B_STG;
        const uint32_t BloB  = BhiB + 8192;
#pragma unroll
        for (int ks = 0; ks < 2; ks++) {
            uint32_t ahi[2][4], alo[2][4];
#pragma unroll
            for (int mt = 0; mt < 2; mt++) {
                int R = wm * 32 + mt * 16 + (lane & 15);
                int gh = 2 * ks + (lane >> 4);
                ldm_x4(ahi[mt], Abase + a_off(R, gh));
                ldm_x4(alo[mt], Abase + a_off(R, gh + 4));
            }
            int kk = 16 * ks + (lane & 15);
#pragma unroll
            for (int ntp = 0; ntp < 4; ntp++) {
                int gn = wn * 8 + ntp * 2 + (lane >> 4);
                uint32_t bhi[4], blo[4];
                ldm_x4t(bhi, BhiB + b_off2(kk, gn));
                ldm_x4t(blo, BloB + b_off2(kk, gn));
#pragma unroll
                for (int mt = 0; mt < 2; mt++) {
                    mma_bf16(acc[mt][ntp * 2],     ahi[mt], bhi);
                    mma_bf16(acc[mt][ntp * 2 + 1], ahi[mt], bhi + 2);
                    mma_bf16(acc[mt][ntp * 2],     ahi[mt], blo);
                    mma_bf16(acc[mt][ntp * 2 + 1], ahi[mt], blo + 2);
                    mma_bf16(acc[mt][ntp * 2],     alo[mt], bhi);
                    mma_bf16(acc[mt][ntp * 2 + 1], alo[mt], bhi + 2);
                }
            }
        }
        __syncthreads();
    }

    // ---- epilogue: store wh, fused s/d dot products ----
    float sacc[2][2] = {{0, 0}, {0, 0}}, dacc[2][2] = {{0, 0}, {0, 0}};
#pragma unroll
    for (int mt = 0; mt < 2; mt++) {
        int rbase = R0 + wm * 32 + mt * 16 + grp;
#pragma unroll
        for (int nt = 0; nt < 8; nt++) {
            int col = wn * 64 + nt * 8 + tig * 2;
            float* cf = acc[mt][nt];
            sacc[mt][0] += cf[0] * a_s[col] + cf[1] * a_s[col + 1];
            sacc[mt][1] += cf[2] * a_s[col] + cf[3] * a_s[col + 1];
            dacc[mt][0] += cf[0] * a_d[col] + cf[1] * a_d[col + 1];
            dacc[mt][1] += cf[2] * a_d[col] + cf[3] * a_d[col + 1];
            *(float2*)&g_wh[(size_t)rbase * DOUT_ + col]       = make_float2(cf[0], cf[1]);
            *(float2*)&g_wh[(size_t)(rbase + 8) * DOUT_ + col] = make_float2(cf[2], cf[3]);
        }
    }
    // reduce across the 4 threads-in-group (cols), then combine across wn warps
#pragma unroll
    for (int mt = 0; mt < 2; mt++)
#pragma unroll
        for (int h = 0; h < 2; h++) {
            sacc[mt][h] += __shfl_xor_sync(0xffffffffu, sacc[mt][h], 1);
            sacc[mt][h] += __shfl_xor_sync(0xffffffffu, sacc[mt][h], 2);
            dacc[mt][h] += __shfl_xor_sync(0xffffffffu, dacc[mt][h], 1);
            dacc[mt][h] += __shfl_xor_sync(0xffffffffu, dacc[mt][h], 2);
        }
    if (tig == 0) {
#pragma unroll
        for (int mt = 0; mt < 2; mt++) {
            int r = wm * 32 + mt * 16 + grp;
            atomicAdd(&s_sm[r], sacc[mt][0]);
            atomicAdd(&s_sm[r + 8], sacc[mt][1]);
            atomicAdd(&d_sm[r], dacc[mt][0]);
            atomicAdd(&d_sm[r + 8], dacc[mt][1]);
        }
    }
    __syncthreads();
    if (tid < 128) {
        g_s[R0 + tid] = s_sm[tid];
        g_d[R0 + tid] = d_sm[tid];
    }
}

// ---------------- per-graph column sums of wh (deg==0 fallback) -----------
__global__ __launch_bounds__(128) void colsum_kernel() {
    int b = blockIdx.x / 32;
    int base = blockIdx.x * 128;
    float acc = 0.0f;
    for (int r = 0; r < 128; r++)
        acc += g_wh[(size_t)(base + r) * DOUT_ + threadIdx.x];
    atomicAdd(&g_sumwh[b * DOUT_ + threadIdx.x], acc);
}

// ---------------- attention SpMM ----------------
__global__ __launch_bounds__(256) void attn_kernel() {
    __shared__ float sh_p[8][MAXDEG];
    __shared__ int   sh_j[8][MAXDEG];
    int gw = (blockIdx.x * blockDim.x + threadIdx.x) >> 5;
    int lane = threadIdx.x & 31;
    int w = (threadIdx.x >> 5);
    if (gw >= B_ * N_) return;
    int b = gw / N_, i = gw % N_;
    int deg = g_deg[i];

    float4* outr = (float4*)&g_out[(size_t)gw * DOUT_];

    if (deg == 0) {
        const float4* sw = (const float4*)&g_sumwh[b * DOUT_];
        float4 m = sw[lane];
        float inv = 1.0f / (float)N_;
        outr[lane] = make_float4(m.x * inv, m.y * inv, m.z * inv, m.w * inv);
        return;
    }

    float si = g_s[gw];
    float mx = NEG_BIG;
    for (int t = lane; t < deg; t += 32) {
        int j = g_cols[i * MAXDEG + t];
        float e = si + g_d[(size_t)b * N_ + j];
        e = e > 0.0f ? e : 0.01f * e;
        sh_j[w][t] = j;
        sh_p[w][t] = e;
        mx = fmaxf(mx, e);
    }
#pragma unroll
    for (int off = 16; off > 0; off >>= 1)
        mx = fmaxf(mx, __shfl_xor_sync(0xffffffffu, mx, off));
    __syncwarp();

    float se = 0.0f;
    for (int t = lane; t < deg; t += 32) {
        float p = expf(sh_p[w][t] - mx);
        sh_p[w][t] = p;
        se += p;
    }
#pragma unroll
    for (int off = 16; off > 0; off >>= 1)
        se += __shfl_xor_sync(0xffffffffu, se, off);
    float inv = 1.0f / se;
    __syncwarp();

    float4 acc = make_float4(0.f, 0.f, 0.f, 0.f);
    for (int k = 0; k < deg; k++) {
        float p = sh_p[w][k] * inv;
        int j = sh_j[w][k];
        float4 v = ((const float4*)&g_wh[((size_t)b * N_ + j) * DOUT_])[lane];
        acc.x += p * v.x; acc.y += p * v.y; acc.z += p * v.z; acc.w += p * v.w;
    }
    outr[lane] = acc;
}

// ---------------- final: y = relu(adj @ out) ----------------
__global__ __launch_bounds__(256) void final_kernel(float* __restrict__ y) {
    int gw = (blockIdx.x * blockDim.x + threadIdx.x) >> 5;
    int lane = threadIdx.x & 31;
    if (gw >= B_ * N_) return;
    int b = gw / N_, i = gw % N_;
    int deg = g_deg[i];

    float4 acc = make_float4(0.f, 0.f, 0.f, 0.f);
    for (int k = 0; k < deg; k++) {
        int j = g_cols[i * MAXDEG + k];
        float4 v = ((const float4*)&g_out[((size_t)b * N_ + j) * DOUT_])[lane];
        acc.x += v.x; acc.y += v.y; acc.z += v.z; acc.w += v.w;
    }
    float4 r = make_float4(fmaxf(acc.x, 0.f), fmaxf(acc.y, 0.f),
                           fmaxf(acc.z, 0.f), fmaxf(acc.w, 0.f));
    ((float4*)&y[(size_t)gw * DOUT_])[lane] = r;
}

// ---------------- launch ----------------
extern "C" void kernel_launch(void* const* d_in, const int* in_sizes, int n_in,
                              void* d_out, int out_size) {
    const float* x   = (const float*)d_in[0];  // (B, N, DIN)
    const float* adj = (const float*)d_in[1];  // (N, N)
    const float* wts = (const float*)d_in[2];  // (DIN, DOUT)
    const float* a   = (const float*)d_in[3];  // (2*DOUT, 1)
    float* y = (float*)d_out;

    static int smem_set = 0;
    if (!smem_set) {
        cudaFuncSetAttribute(gemm_hmma_kernel,
                             cudaFuncAttributeMaxDynamicSharedMemorySize, SMEM_TOTAL);
        smem_set = 1;
    }

    zero_kernel<<<1, 512>>>();
    csr_build_kernel<<<N_ / 8, 256>>>(adj);
    gemm_hmma_kernel<<<(B_ * N_) / 128, 256, SMEM_TOTAL>>>(x, wts, a);
    colsum_kernel<<<(B_ * N_) / 128, 128>>>();
    attn_kernel<<<(B_ * N_) / 8, 256>>>();
    final_kernel<<<(B_ * N_) / 8, 256>>>(y);
}

// round 4
// speedup vs baseline: 1.8283x; 1.0485x over previous
#include <cuda_runtime.h>
#include <cuda_bf16.h>
#include <math.h>
#include <stdint.h>

#define B_    4
#define N_    4096
#define DIN_  512
#define DOUT_ 128
#define MAXDEG 256
#define NEG_BIG -1e30f

// ---------------- scratch (static device memory; no allocs) ----------------
__device__ float g_wh[B_ * N_ * DOUT_];     // x @ W            (8 MB)
__device__ float g_out[B_ * N_ * DOUT_];    // att @ wh         (8 MB)
__device__ float g_s[B_ * N_];              // wh @ a_src
__device__ float g_d[B_ * N_];              // wh @ a_dst
__device__ float g_sumwh[B_ * DOUT_];       // per-graph colsum (deg==0 fallback)
__device__ int   g_cols[N_ * MAXDEG];
__device__ int   g_deg[N_];

// ============================ helpers =======================================
__device__ __forceinline__ uint32_t smem_u32(const void* p) {
    uint32_t a;
    asm("{ .reg .u64 t; cvta.to.shared.u64 t, %1; cvt.u32.u64 %0, t; }" : "=r"(a) : "l"(p));
    return a;
}
__device__ __forceinline__ void ldm_x4(uint32_t* f, uint32_t addr) {
    asm volatile("ldmatrix.sync.aligned.m8n8.x4.shared.b16 {%0,%1,%2,%3}, [%4];"
                 : "=r"(f[0]), "=r"(f[1]), "=r"(f[2]), "=r"(f[3]) : "r"(addr));
}
__device__ __forceinline__ void ldm_x4t(uint32_t* f, uint32_t addr) {
    asm volatile("ldmatrix.sync.aligned.m8n8.x4.trans.shared.b16 {%0,%1,%2,%3}, [%4];"
                 : "=r"(f[0]), "=r"(f[1]), "=r"(f[2]), "=r"(f[3]) : "r"(addr));
}
__device__ __forceinline__ void mma_bf16(float* c, const uint32_t* a, const uint32_t* b) {
    asm volatile(
        "mma.sync.aligned.m16n8k16.row.col.f32.bf16.bf16.f32 "
        "{%0,%1,%2,%3}, {%4,%5,%6,%7}, {%8,%9}, {%0,%1,%2,%3};"
        : "+f"(c[0]), "+f"(c[1]), "+f"(c[2]), "+f"(c[3])
        : "r"(a[0]), "r"(a[1]), "r"(a[2]), "r"(a[3]), "r"(b[0]), "r"(b[1]));
}
__device__ __forceinline__ uint32_t pack_bf16(float x, float y) {
    __nv_bfloat16 hx = __float2bfloat16_rn(x);
    __nv_bfloat16 hy = __float2bfloat16_rn(y);
    return ((uint32_t)__bfloat16_as_ushort(hy) << 16) | __bfloat16_as_ushort(hx);
}

// =============== CSR build (+ zero of g_sumwh folded in) ===================
__global__ void csr_build_kernel(const float* __restrict__ adj) {
    if (blockIdx.x == 0 && threadIdx.x < B_ * DOUT_) g_sumwh[threadIdx.x] = 0.0f;

    int warp = (blockIdx.x * blockDim.x + threadIdx.x) >> 5;
    int lane = threadIdx.x & 31;
    if (warp >= N_) return;
    const float4* row = (const float4*)(adj + (size_t)warp * N_);
    int cnt = 0;
    for (int base = 0; base < N_; base += 256) {
        // two loads in flight
        float4 v0 = row[(base >> 2) + lane];
        float4 v1 = row[(base >> 2) + 32 + lane];
        float c8[8] = {v0.x, v0.y, v0.z, v0.w, v1.x, v1.y, v1.z, v1.w};
#pragma unroll
        for (int h = 0; h < 2; h++) {
#pragma unroll
            for (int c = 0; c < 4; c++) {
                float f = c8[h * 4 + c];
                unsigned m = __ballot_sync(0xffffffffu, f > 0.0f);
                if (f > 0.0f) {
                    int pos = cnt + __popc(m & ((1u << lane) - 1u));
                    if (pos < MAXDEG)
                        g_cols[warp * MAXDEG + pos] = base + h * 128 + lane * 4 + c;
                }
                cnt += __popc(m);
            }
        }
    }
    if (lane == 0) g_deg[warp] = cnt < MAXDEG ? cnt : MAXDEG;
}

// ============ HMMA GEMM: wh = x @ W  (M=16384, N=128, K=512) ===============
// 128x128 CTA tile, 8 warps of 32x64. K chunks of 32, bf16 3-term split
// (hi*hi + hi*lo + lo*hi), double-buffered smem + register prefetch.
// Fused epilogue: s = wh@a_src, d = wh@a_dst, per-graph column sums.
#define KC 32
#define NCH (DIN_ / KC)          // 16 chunks
#define A_STG 16384              // 128 rows * 128B
#define B_STG 16384              // hi 8KB + lo 8KB
#define SM_A 0
#define SM_B (2 * A_STG)
#define SM_SD (SM_B + 2 * B_STG)          // s_sm[128], d_sm[128]
#define SM_AV (SM_SD + 1024)              // a_s[128], a_d[128]
#define SM_CS (SM_AV + 1024)              // cs[128] column sums
#define SMEM_TOTAL (SM_CS + 512)

__device__ __forceinline__ uint32_t a_off(int r, int gran) {
    return (uint32_t)(r * 128 + ((gran ^ (r & 7)) << 4));
}
__device__ __forceinline__ uint32_t b_off2(int k, int gran) {
    return (uint32_t)(k * 256 + ((gran ^ (k & 7)) << 4));
}

__global__ __launch_bounds__(256, 1) void gemm_hmma_kernel(
    const float* __restrict__ x, const float* __restrict__ W,
    const float* __restrict__ a) {
    extern __shared__ char smem[];
    const uint32_t sb = smem_u32(smem);
    const int tid = threadIdx.x;
    const int wid = tid >> 5, lane = tid & 31;
    const int wm = wid >> 1, wn = wid & 1;   // warp tile: rows wm*32, cols wn*64
    const int tig = lane & 3, grp = lane >> 2;

    float* s_sm = (float*)(smem + SM_SD);
    float* d_sm = (float*)(smem + SM_SD + 512);
    float* a_s  = (float*)(smem + SM_AV);
    float* a_d  = (float*)(smem + SM_AV + 512);
    float* cs   = (float*)(smem + SM_CS);
    if (tid < 128) {
        s_sm[tid] = 0.0f; d_sm[tid] = 0.0f; cs[tid] = 0.0f;
        a_s[tid] = a[tid]; a_d[tid] = a[DOUT_ + tid];
    }

    const int R0 = blockIdx.x * 128;
    // global load coords
    const int arow = tid >> 1, akoff = (tid & 1) * 16;
    const int bk = tid >> 3,  bn0 = (tid & 7) * 16;
    const float* pA = x + (size_t)(R0 + arow) * DIN_ + akoff;
    const float* pB = W + (size_t)bk * DOUT_ + bn0;

    float acc[2][8][4];
#pragma unroll
    for (int i = 0; i < 2; i++)
#pragma unroll
        for (int j = 0; j < 8; j++)
#pragma unroll
            for (int q = 0; q < 4; q++) acc[i][j][q] = 0.0f;

    float4 ra[4], rb[4];
    // prologue: chunk 0
#pragma unroll
    for (int i = 0; i < 4; i++) ra[i] = *(const float4*)(pA + i * 4);
#pragma unroll
    for (int i = 0; i < 4; i++) rb[i] = *(const float4*)(pB + i * 4);

    for (int c = 0; c < NCH; c++) {
        const int buf = c & 1;
        char* Abuf = smem + SM_A + buf * A_STG;
        char* Bhi  = smem + SM_B + buf * B_STG;
        char* Blo  = Bhi + 8192;

        // store prefetched chunk c into smem (converted)
        {
            const float* fa = (const float*)ra;
#pragma unroll
            for (int p = 0; p < 8; p++) {
                float f0 = fa[2 * p], f1 = fa[2 * p + 1];
                uint32_t hv = pack_bf16(f0, f1);
                float l0 = f0 - __bfloat162float(__float2bfloat16_rn(f0));
                float l1 = f1 - __bfloat162float(__float2bfloat16_rn(f1));
                uint32_t lv = pack_bf16(l0, l1);
                int kl = akoff + 2 * p;
                int gr = kl >> 3, wi = (kl & 7) * 2;
                *(uint32_t*)(Abuf + a_off(arow, gr) + wi)     = hv;
                *(uint32_t*)(Abuf + a_off(arow, gr + 4) + wi) = lv;
            }
            const float* fb = (const float*)rb;
#pragma unroll
            for (int p = 0; p < 8; p++) {
                float f0 = fb[2 * p], f1 = fb[2 * p + 1];
                uint32_t hv = pack_bf16(f0, f1);
                float l0 = f0 - __bfloat162float(__float2bfloat16_rn(f0));
                float l1 = f1 - __bfloat162float(__float2bfloat16_rn(f1));
                uint32_t lv = pack_bf16(l0, l1);
                int n = bn0 + 2 * p;
                int gr = n >> 3, wi = (n & 7) * 2;
                *(uint32_t*)(Bhi + b_off2(bk, gr) + wi) = hv;
                *(uint32_t*)(Blo + b_off2(bk, gr) + wi) = lv;
            }
        }
        __syncthreads();

        // prefetch chunk c+1 into regs
        if (c + 1 < NCH) {
            const float* qA = pA + (c + 1) * KC;
            const float* qB = pB + (size_t)(c + 1) * KC * DOUT_;
#pragma unroll
            for (int i = 0; i < 4; i++) ra[i] = *(const float4*)(qA + i * 4);
#pragma unroll
            for (int i = 0; i < 4; i++) rb[i] = *(const float4*)(qB + i * 4);
        }

        // ---- MMA on chunk c ----
        const uint32_t Abase = sb + SM_A + buf * A_STG;
        const uint32_t BhiB  = sb + SM_B + buf * B_STG;
        const uint32_t BloB  = BhiB + 8192;
#pragma unroll
        for (int ks = 0; ks < 2; ks++) {
            uint32_t ahi[2][4], alo[2][4];
#pragma unroll
            for (int mt = 0; mt < 2; mt++) {
                int R = wm * 32 + mt * 16 + (lane & 15);
                int gh = 2 * ks + (lane >> 4);
                ldm_x4(ahi[mt], Abase + a_off(R, gh));
                ldm_x4(alo[mt], Abase + a_off(R, gh + 4));
            }
            int kk = 16 * ks + (lane & 15);
#pragma unroll
            for (int ntp = 0; ntp < 4; ntp++) {
                int gn = wn * 8 + ntp * 2 + (lane >> 4);
                uint32_t bhi[4], blo[4];
                ldm_x4t(bhi, BhiB + b_off2(kk, gn));
                ldm_x4t(blo, BloB + b_off2(kk, gn));
#pragma unroll
                for (int mt = 0; mt < 2; mt++) {
                    mma_bf16(acc[mt][ntp * 2],     ahi[mt], bhi);
                    mma_bf16(acc[mt][ntp * 2 + 1], ahi[mt], bhi + 2);
                    mma_bf16(acc[mt][ntp * 2],     ahi[mt], blo);
                    mma_bf16(acc[mt][ntp * 2 + 1], ahi[mt], blo + 2);
                    mma_bf16(acc[mt][ntp * 2],     alo[mt], bhi);
                    mma_bf16(acc[mt][ntp * 2 + 1], alo[mt], bhi + 2);
                }
            }
        }
        __syncthreads();
    }

    // ---- epilogue: store wh, fused s/d dots + column sums ----
    float sacc[2][2] = {{0, 0}, {0, 0}}, dacc[2][2] = {{0, 0}, {0, 0}};
#pragma unroll
    for (int mt = 0; mt < 2; mt++) {
        int rbase = R0 + wm * 32 + mt * 16 + grp;
#pragma unroll
        for (int nt = 0; nt < 8; nt++) {
            int col = wn * 64 + nt * 8 + tig * 2;
            float* cf = acc[mt][nt];
            sacc[mt][0] += cf[0] * a_s[col] + cf[1] * a_s[col + 1];
            sacc[mt][1] += cf[2] * a_s[col] + cf[3] * a_s[col + 1];
            dacc[mt][0] += cf[0] * a_d[col] + cf[1] * a_d[col + 1];
            dacc[mt][1] += cf[2] * a_d[col] + cf[3] * a_d[col + 1];
            *(float2*)&g_wh[(size_t)rbase * DOUT_ + col]       = make_float2(cf[0], cf[1]);
            *(float2*)&g_wh[(size_t)(rbase + 8) * DOUT_ + col] = make_float2(cf[2], cf[3]);

            // column sums: reduce (cf0+cf2) and (cf1+cf3) across grp (8 rows)
            float v0 = cf[0] + cf[2];
            float v1 = cf[1] + cf[3];
#pragma unroll
            for (int off = 16; off >= 4; off >>= 1) {
                v0 += __shfl_down_sync(0xffffffffu, v0, off);
                v1 += __shfl_down_sync(0xffffffffu, v1, off);
            }
            if (lane < 4) {
                atomicAdd(&cs[col], v0);
                atomicAdd(&cs[col + 1], v1);
            }
        }
    }
    // reduce s/d across the 4 threads-in-group (cols)
#pragma unroll
    for (int mt = 0; mt < 2; mt++)
#pragma unroll
        for (int h = 0; h < 2; h++) {
            sacc[mt][h] += __shfl_xor_sync(0xffffffffu, sacc[mt][h], 1);
            sacc[mt][h] += __shfl_xor_sync(0xffffffffu, sacc[mt][h], 2);
            dacc[mt][h] += __shfl_xor_sync(0xffffffffu, dacc[mt][h], 1);
            dacc[mt][h] += __shfl_xor_sync(0xffffffffu, dacc[mt][h], 2);
        }
    if (tig == 0) {
#pragma unroll
        for (int mt = 0; mt < 2; mt++) {
            int r = wm * 32 + mt * 16 + grp;
            atomicAdd(&s_sm[r], sacc[mt][0]);
            atomicAdd(&s_sm[r + 8], sacc[mt][1]);
            atomicAdd(&d_sm[r], dacc[mt][0]);
            atomicAdd(&d_sm[r + 8], dacc[mt][1]);
        }
    }
    __syncthreads();
    if (tid < 128) {
        g_s[R0 + tid] = s_sm[tid];
        g_d[R0 + tid] = d_sm[tid];
        int b = R0 / N_;
        atomicAdd(&g_sumwh[b * DOUT_ + tid], cs[tid]);
    }
}

// ---------------- attention SpMM ----------------
__global__ __launch_bounds__(256) void attn_kernel() {
    __shared__ float sh_p[8][MAXDEG];
    __shared__ int   sh_j[8][MAXDEG];
    int gw = (blockIdx.x * blockDim.x + threadIdx.x) >> 5;
    int lane = threadIdx.x & 31;
    int w = (threadIdx.x >> 5);
    if (gw >= B_ * N_) return;
    int b = gw / N_, i = gw % N_;
    int deg = g_deg[i];

    float4* outr = (float4*)&g_out[(size_t)gw * DOUT_];

    if (deg == 0) {
        const float4* sw = (const float4*)&g_sumwh[b * DOUT_];
        float4 m = sw[lane];
        float inv = 1.0f / (float)N_;
        outr[lane] = make_float4(m.x * inv, m.y * inv, m.z * inv, m.w * inv);
        return;
    }

    float si = g_s[gw];
    float mx = NEG_BIG;
    for (int t = lane; t < deg; t += 32) {
        int j = g_cols[i * MAXDEG + t];
        float e = si + g_d[(size_t)b * N_ + j];
        e = e > 0.0f ? e : 0.01f * e;
        sh_j[w][t] = j;
        sh_p[w][t] = e;
        mx = fmaxf(mx, e);
    }
#pragma unroll
    for (int off = 16; off > 0; off >>= 1)
        mx = fmaxf(mx, __shfl_xor_sync(0xffffffffu, mx, off));
    __syncwarp();

    float se = 0.0f;
    for (int t = lane; t < deg; t += 32) {
        float p = expf(sh_p[w][t] - mx);
        sh_p[w][t] = p;
        se += p;
    }
#pragma unroll
    for (int off = 16; off > 0; off >>= 1)
        se += __shfl_xor_sync(0xffffffffu, se, off);
    float inv = 1.0f / se;
    __syncwarp();

    const float4* whb = (const float4*)&g_wh[(size_t)b * N_ * DOUT_];
    float4 acc0 = make_float4(0.f, 0.f, 0.f, 0.f);
    float4 acc1 = make_float4(0.f, 0.f, 0.f, 0.f);
    int k = 0;
    for (; k + 2 <= deg; k += 2) {
        float p0 = sh_p[w][k] * inv,     p1 = sh_p[w][k + 1] * inv;
        int   j0 = sh_j[w][k],           j1 = sh_j[w][k + 1];
        float4 v0 = whb[(size_t)j0 * 32 + lane];
        float4 v1 = whb[(size_t)j1 * 32 + lane];
        acc0.x += p0 * v0.x; acc0.y += p0 * v0.y; acc0.z += p0 * v0.z; acc0.w += p0 * v0.w;
        acc1.x += p1 * v1.x; acc1.y += p1 * v1.y; acc1.z += p1 * v1.z; acc1.w += p1 * v1.w;
    }
    if (k < deg) {
        float p0 = sh_p[w][k] * inv;
        float4 v0 = whb[(size_t)sh_j[w][k] * 32 + lane];
        acc0.x += p0 * v0.x; acc0.y += p0 * v0.y; acc0.z += p0 * v0.z; acc0.w += p0 * v0.w;
    }
    outr[lane] = make_float4(acc0.x + acc1.x, acc0.y + acc1.y,
                             acc0.z + acc1.z, acc0.w + acc1.w);
}

// ---------------- final: y = relu(adj @ out) ----------------
__global__ __launch_bounds__(256) void final_kernel(float* __restrict__ y) {
    int gw = (blockIdx.x * blockDim.x + threadIdx.x) >> 5;
    int lane = threadIdx.x & 31;
    if (gw >= B_ * N_) return;
    int b = gw / N_, i = gw % N_;
    int deg = g_deg[i];

    const float4* outb = (const float4*)&g_out[(size_t)b * N_ * DOUT_];
    float4 acc0 = make_float4(0.f, 0.f, 0.f, 0.f);
    float4 acc1 = make_float4(0.f, 0.f, 0.f, 0.f);
    int k = 0;
    for (; k + 2 <= deg; k += 2) {
        int j0 = g_cols[i * MAXDEG + k], j1 = g_cols[i * MAXDEG + k + 1];
        float4 v0 = outb[(size_t)j0 * 32 + lane];
        float4 v1 = outb[(size_t)j1 * 32 + lane];
        acc0.x += v0.x; acc0.y += v0.y; acc0.z += v0.z; acc0.w += v0.w;
        acc1.x += v1.x; acc1.y += v1.y; acc1.z += v1.z; acc1.w += v1.w;
    }
    if (k < deg) {
        float4 v0 = outb[(size_t)g_cols[i * MAXDEG + k] * 32 + lane];
        acc0.x += v0.x; acc0.y += v0.y; acc0.z += v0.z; acc0.w += v0.w;
    }
    float4 r = make_float4(fmaxf(acc0.x + acc1.x, 0.f), fmaxf(acc0.y + acc1.y, 0.f),
                           fmaxf(acc0.z + acc1.z, 0.f), fmaxf(acc0.w + acc1.w, 0.f));
    ((float4*)&y[(size_t)gw * DOUT_])[lane] = r;
}

// ---------------- launch ----------------
extern "C" void kernel_launch(void* const* d_in, const int* in_sizes, int n_in,
                              void* d_out, int out_size) {
    const float* x   = (const float*)d_in[0];  // (B, N, DIN)
    const float* adj = (const float*)d_in[1];  // (N, N)
    const float* wts = (const float*)d_in[2];  // (DIN, DOUT)
    const float* a   = (const float*)d_in[3];  // (2*DOUT, 1)
    float* y = (float*)d_out;

    static int smem_set = 0;
    if (!smem_set) {
        cudaFuncSetAttribute(gemm_hmma_kernel,
                             cudaFuncAttributeMaxDynamicSharedMemorySize, SMEM_TOTAL);
        smem_set = 1;
    }

    csr_build_kernel<<<N_ / 8, 256>>>(adj);
    gemm_hmma_kernel<<<(B_ * N_) / 128, 256, SMEM_TOTAL>>>(x, wts, a);
    attn_kernel<<<(B_ * N_) / 8, 256>>>();
    final_kernel<<<(B_ * N_) / 8, 256>>>(y);
}